// round 5
// baseline (speedup 1.0000x reference)
#include <cuda_runtime.h>
#include <stdint.h>

#define BATCH 16
#define NPTS  131072
#define NSAMP 1024
#define BPB   8                      // blocks per batch = cluster size
#define PTS   (NPTS / BPB)           // 16384 points per block
#define TH    1024                   // threads per block
#define KK    (PTS / (4 * TH))       // 4 x 4-point chunks per thread

#define EXCH_FLOATS 272              // 1024B exch slots + 64B mbarrier/pad
#define SMEM_BYTES  ((EXCH_FLOATS + PTS * 3) * (int)sizeof(float))  // 197696

#define OFF_SCALE (BATCH * NSAMP * 3)   // 49152
#define OFF_IDX   (OFF_SCALE + BATCH)   // 49168

typedef unsigned long long u64;
typedef unsigned int       u32;

// device scratch (no allocations allowed)
__device__ int    g_idx[BATCH * NSAMP];
__device__ float  g_scale[BATCH];
__device__ float  g_psum[BATCH][BPB][3];
__device__ float  g_pmax[BATCH][BPB];

// ---------------------------------------------------------------------------
// helpers
// ---------------------------------------------------------------------------
__device__ __forceinline__ u64 add2(u64 a, u64 b) {
    u64 d; asm("add.rn.f32x2 %0,%1,%2;" : "=l"(d) : "l"(a), "l"(b)); return d;
}
__device__ __forceinline__ u64 mul2(u64 a, u64 b) {
    u64 d; asm("mul.rn.f32x2 %0,%1,%2;" : "=l"(d) : "l"(a), "l"(b)); return d;
}
__device__ __forceinline__ void unpack2(u64 v, int& lo, int& hi) {
    asm("mov.b64 {%0,%1},%2;" : "=r"(lo), "=r"(hi) : "l"(v));
}
__device__ __forceinline__ u64 bcast2(float v) {
    u32 b = __float_as_uint(v); return ((u64)b << 32) | (u64)b;
}
__device__ __forceinline__ u32 smem_u32(const void* p) {
    u32 a; asm("{ .reg .u64 t; cvta.to.shared.u64 t,%1; cvt.u32.u64 %0,t; }"
               : "=r"(a) : "l"(p));
    return a;
}
__device__ __forceinline__ u32 mapa_rank(u32 addr, u32 rank) {
    u32 r; asm("mapa.shared::cluster.u32 %0,%1,%2;" : "=r"(r) : "r"(addr), "r"(rank));
    return r;
}
// arrive on a PEER CTA's mbarrier; .release.cluster orders our prior DSMEM store
__device__ __forceinline__ void mbar_arrive_remote(u32 remote_addr) {
    asm volatile("mbarrier.arrive.release.cluster.shared::cluster.b64 _,[%0];"
                 :: "r"(remote_addr) : "memory");
}
// wait for local mbarrier phase completion with acquire.cluster
__device__ __forceinline__ void mbar_wait_parity(u32 addr, u32 parity) {
    asm volatile(
        "{\n\t.reg .pred P;\n\t"
        "W%=:\n\t"
        "mbarrier.try_wait.parity.acquire.cluster.shared::cta.b64 P,[%0],%1,0x989680;\n\t"
        "@!P bra W%=;\n\t}"
        :: "r"(addr), "r"(parity) : "memory");
}

// ---------------------------------------------------------------------------
// Scale pass 1: per-slice partial sums (deterministic tree)
// ---------------------------------------------------------------------------
__global__ void __launch_bounds__(512, 1)
scale1_kernel(const float* __restrict__ mesh)
{
    const int b = blockIdx.x / BPB, s = blockIdx.x % BPB, tid = threadIdx.x;
    const float* base = mesh + (size_t)b * NPTS * 3 + (size_t)s * PTS * 3;

    float sx = 0.f, sy = 0.f, sz = 0.f;
    for (int p = tid; p < PTS; p += 512) {
        const float* q = base + (size_t)p * 3;
        sx += q[0]; sy += q[1]; sz += q[2];
    }
    __shared__ float red[3][16];
    #pragma unroll
    for (int off = 16; off; off >>= 1) {
        sx += __shfl_xor_sync(0xffffffffu, sx, off);
        sy += __shfl_xor_sync(0xffffffffu, sy, off);
        sz += __shfl_xor_sync(0xffffffffu, sz, off);
    }
    const int w = tid >> 5, l = tid & 31;
    if (l == 0) { red[0][w] = sx; red[1][w] = sy; red[2][w] = sz; }
    __syncthreads();
    if (w == 0 && l < 16) {
        sx = red[0][l]; sy = red[1][l]; sz = red[2][l];
        #pragma unroll
        for (int off = 8; off; off >>= 1) {
            sx += __shfl_xor_sync(0xffffffffu, sx, off);
            sy += __shfl_xor_sync(0xffffffffu, sy, off);
            sz += __shfl_xor_sync(0xffffffffu, sz, off);
        }
        if (l == 0) {
            g_psum[b][s][0] = sx; g_psum[b][s][1] = sy; g_psum[b][s][2] = sz;
        }
    }
}

// ---------------------------------------------------------------------------
// Scale pass 2: finalize mean (fixed order), partial max of dist^2 per slice
// ---------------------------------------------------------------------------
__global__ void __launch_bounds__(512, 1)
scale2_kernel(const float* __restrict__ mesh)
{
    const int b = blockIdx.x / BPB, s = blockIdx.x % BPB, tid = threadIdx.x;

    float mx = 0.f, my = 0.f, mz = 0.f;
    #pragma unroll
    for (int i = 0; i < BPB; i++) {
        mx += g_psum[b][i][0]; my += g_psum[b][i][1]; mz += g_psum[b][i][2];
    }
    const float cx = mx * (1.0f / NPTS), cy = my * (1.0f / NPTS), cz = mz * (1.0f / NPTS);

    const float* base = mesh + (size_t)b * NPTS * 3 + (size_t)s * PTS * 3;
    float m = 0.f;
    for (int p = tid; p < PTS; p += 512) {
        const float* q = base + (size_t)p * 3;
        float dx = q[0] - cx, dy = q[1] - cy, dz = q[2] - cz;
        m = fmaxf(m, dx * dx + dy * dy + dz * dz);
    }
    __shared__ float red[16];
    #pragma unroll
    for (int off = 16; off; off >>= 1)
        m = fmaxf(m, __shfl_xor_sync(0xffffffffu, m, off));
    const int w = tid >> 5, l = tid & 31;
    if (l == 0) red[w] = m;
    __syncthreads();
    if (w == 0 && l < 16) {
        m = red[l];
        #pragma unroll
        for (int off = 8; off; off >>= 1)
            m = fmaxf(m, __shfl_xor_sync(0xffffffffu, m, off));
        if (l == 0) g_pmax[b][s] = m;
    }
}

// ---------------------------------------------------------------------------
// Scale pass 3: final max -> sqrt, write scale
// ---------------------------------------------------------------------------
__global__ void scale3_kernel(float* __restrict__ out)
{
    const int b = blockIdx.x, l = threadIdx.x;
    float m = (l < BPB) ? g_pmax[b][l] : 0.f;
    #pragma unroll
    for (int off = 4; off; off >>= 1)
        m = fmaxf(m, __shfl_xor_sync(0xffffffffu, m, off));
    if (l == 0) {
        float sc = __fsqrt_rn(m);        // sqrt(max) == max(sqrt): monotone
        g_scale[b] = sc;
        out[OFF_SCALE + b] = sc;
    }
}

// ---------------------------------------------------------------------------
// FPS: 8-CTA cluster per batch, 1024 threads (occ 50%), mbarrier exchange
// ---------------------------------------------------------------------------
__global__ void __launch_bounds__(TH, 1) __cluster_dims__(BPB, 1, 1)
fps_kernel(const float* __restrict__ mesh, const int* __restrict__ finit)
{
    extern __shared__ float sm[];
    float4 (*ex)[BPB][2] = (float4(*)[BPB][2])sm;    // [2][BPB][2] double-buffered
    u64* mbar = (u64*)(sm + 256);                    // 8B mbarrier at offset 1024B
    float* sx = sm + EXCH_FLOATS;
    float* sy = sx + PTS;
    float* sz = sy + PTS;

    const int blk = blockIdx.x;
    const int b = blk / BPB;
    const int s = blk - b * BPB;                     // == cluster_ctarank
    const int tid = threadIdx.x;
    const int w = tid >> 5, l = tid & 31;

    const float* mb = mesh + (size_t)b * NPTS * 3;
    const u32 ex_base = smem_u32(sm);                // byte addr of ex[0][0]
    const u32 mbar_addr = ex_base + 1024;

    // init local mbarrier: 8 arrivals (one per CTA) complete a phase
    if (tid == 0) {
        asm volatile("mbarrier.init.shared.b64 [%0],%1;" :: "r"(mbar_addr), "r"(BPB)
                     : "memory");
    }

    // stage this block's xyz slice into SMEM (SoA, one-time)
    {
        const float* gsrc = mb + (size_t)s * PTS * 3;
        for (int e = tid; e < PTS * 3; e += TH) {
            float v = gsrc[e];
            int p = e / 3;
            int c = e - 3 * p;
            sx[c * PTS + p] = v;
        }
    }

    // per-thread min-distances as int bit patterns (all values >= 0)
    int di[4 * KK];
    #pragma unroll
    for (int k = 0; k < 4 * KK; k++) di[k] = __float_as_int(1e10f);

    int fidx = finit[b];
    float cx = mb[(size_t)fidx * 3 + 0];
    float cy = mb[(size_t)fidx * 3 + 1];
    float cz = mb[(size_t)fidx * 3 + 2];

    __shared__ u64   skey[TH / 32];
    __shared__ float sbc[4];          // broadcast: idx_bits, cx, cy, cz

    __syncthreads();
    // all CTAs' mbarriers must be initialized before any peer can arrive on them
    asm volatile("barrier.cluster.arrive.aligned;" ::: "memory");
    asm volatile("barrier.cluster.wait.aligned;"   ::: "memory");

    const ulonglong2* sxp = (const ulonglong2*)sx;
    const ulonglong2* syp = (const ulonglong2*)sy;
    const ulonglong2* szp = (const ulonglong2*)sz;

    for (int t = 0; t < NSAMP; ++t) {
        if (s == 0 && tid == 0) g_idx[b * NSAMP + t] = fidx;   // record BEFORE update
        if (t == NSAMP - 1) break;                             // uniform across cluster

        const u64 ncx = bcast2(-cx), ncy = bcast2(-cy), ncz = bcast2(-cz);

        int bvi = -1;            // int compare == float compare for nonneg floats
        int bp  = 0x7fffffff;

        #pragma unroll
        for (int k = 0; k < KK; k++) {
            const int c = k * TH + tid;
            ulonglong2 X = sxp[c];
            ulonglong2 Y = syp[c];
            ulonglong2 Z = szp[c];
            const int base = s * PTS + 4 * c;
            {   // points base, base+1
                u64 dx = add2(X.x, ncx), dy = add2(Y.x, ncy), dz = add2(Z.x, ncz);
                u64 d2 = add2(add2(mul2(dx, dx), mul2(dy, dy)), mul2(dz, dz));
                int a0, a1; unpack2(d2, a0, a1);
                int n0 = min(a0, di[4 * k + 0]); di[4 * k + 0] = n0;
                int n1 = min(a1, di[4 * k + 1]); di[4 * k + 1] = n1;
                if (n0 > bvi) { bvi = n0; bp = base; }
                if (n1 > bvi) { bvi = n1; bp = base + 1; }
            }
            {   // points base+2, base+3
                u64 dx = add2(X.y, ncx), dy = add2(Y.y, ncy), dz = add2(Z.y, ncz);
                u64 d2 = add2(add2(mul2(dx, dx), mul2(dy, dy)), mul2(dz, dz));
                int a0, a1; unpack2(d2, a0, a1);
                int n0 = min(a0, di[4 * k + 2]); di[4 * k + 2] = n0;
                int n1 = min(a1, di[4 * k + 3]); di[4 * k + 3] = n1;
                if (n0 > bvi) { bvi = n0; bp = base + 2; }
                if (n1 > bvi) { bvi = n1; bp = base + 3; }
            }
        }

        // packed key: dist desc, index asc on ties -> single u64 max
        u64 key = ((u64)(u32)bvi << 32) | (u32)(~bp);
        #pragma unroll
        for (int off = 16; off; off >>= 1) {
            u64 ok = __shfl_down_sync(0xffffffffu, key, off);
            if (ok > key) key = ok;
        }
        if (l == 0) skey[w] = key;
        __syncthreads();

        const int par = t & 1;
        if (w == 0) {
            key = skey[l];                                    // TH/32 == 32 lanes
            #pragma unroll
            for (int off = 16; off; off >>= 1) {
                u64 ok = __shfl_down_sync(0xffffffffu, key, off);
                if (ok > key) key = ok;
            }
            key = __shfl_sync(0xffffffffu, key, 0);          // broadcast block winner
            const int gp = (int)(~(u32)key);                 // global-in-batch index
            const int lp = gp - s * PTS;                     // local -> SMEM coords
            const float wx = sx[lp], wy = sy[lp], wz = sz[lp];   // broadcast reads
            if (l < BPB) {
                // push this CTA's candidate into slot[s] of CTA rank l, then
                // arrive on CTA l's mbarrier (release orders the store)
                u32 dst = mapa_rank(ex_base + (u32)((par * BPB + s) * 32), (u32)l);
                asm volatile("st.shared::cluster.v4.f32 [%0],{%1,%2,%3,%4};"
                             :: "r"(dst),
                                "f"(__uint_as_float((u32)key)),
                                "f"(__uint_as_float((u32)(key >> 32))),
                                "f"(wx), "f"(wy) : "memory");
                asm volatile("st.shared::cluster.f32 [%0],%1;"
                             :: "r"(dst + 16), "f"(wz) : "memory");
                mbar_arrive_remote(mapa_rank(mbar_addr, (u32)l));
            }
            // wait for all 8 candidates to land in OUR smem (phase t, parity t&1)
            mbar_wait_parity(mbar_addr, (u32)(t & 1));

            // merge the 8 candidates from LOCAL smem
            if (l < BPB) {
                float4 A  = ex[par][l][0];
                float  Az = ex[par][l][1].x;
                u64 mk = ((u64)__float_as_uint(A.y) << 32) | __float_as_uint(A.x);
                u64 m = mk;
                #pragma unroll
                for (int off = 4; off; off >>= 1) {
                    u64 o = __shfl_down_sync(0x000000ffu, m, off, 8);
                    if (o > m) m = o;
                }
                m = __shfl_sync(0x000000ffu, m, 0, 8);       // broadcast winner key
                unsigned bal = __ballot_sync(0x000000ffu, mk == m);
                int src = __ffs(bal) - 1;                    // keys unique (contain idx)
                float mwx = __shfl_sync(0x000000ffu, A.z, src, 8);
                float mwy = __shfl_sync(0x000000ffu, A.w, src, 8);
                float mwz = __shfl_sync(0x000000ffu, Az,  src, 8);
                if (l == 0) {
                    sbc[0] = __uint_as_float(~(u32)m);
                    sbc[1] = mwx; sbc[2] = mwy; sbc[3] = mwz;
                }
            }
        }
        __syncthreads();

        fidx = (int)__float_as_uint(sbc[0]);
        cx = sbc[1]; cy = sbc[2]; cz = sbc[3];
    }

    // drain: no CTA exits while peers could still target its smem
    asm volatile("barrier.cluster.arrive.aligned;" ::: "memory");
    asm volatile("barrier.cluster.wait.aligned;"   ::: "memory");
}

// ---------------------------------------------------------------------------
// Gather: sample points, normalize, emit idx as float
// ---------------------------------------------------------------------------
__global__ void __launch_bounds__(1024, 1)
gather_kernel(const float* __restrict__ mesh, float* __restrict__ out)
{
    const int b = blockIdx.x;
    const int j = threadIdx.x;
    const int i = g_idx[b * NSAMP + j];
    const float sc = g_scale[b];
    const float* q = mesh + ((size_t)b * NPTS + (size_t)i) * 3;
    const size_t o = ((size_t)b * NSAMP + j) * 3;
    out[o + 0] = __fdiv_rn(q[0], sc);
    out[o + 1] = __fdiv_rn(q[1], sc);
    out[o + 2] = __fdiv_rn(q[2], sc);
    out[OFF_IDX + b * NSAMP + j] = (float)i;   // exact: i < 2^24
}

// ---------------------------------------------------------------------------
extern "C" void kernel_launch(void* const* d_in, const int* in_sizes, int n_in,
                              void* d_out, int out_size)
{
    const float* mesh  = (const float*)d_in[0];
    const int*   finit = (const int*)d_in[1];
    float* out = (float*)d_out;

    cudaFuncSetAttribute(fps_kernel,
                         cudaFuncAttributeMaxDynamicSharedMemorySize, SMEM_BYTES);

    scale1_kernel<<<BATCH * BPB, 512>>>(mesh);
    scale2_kernel<<<BATCH * BPB, 512>>>(mesh);
    scale3_kernel<<<BATCH, 32>>>(out);
    fps_kernel<<<BATCH * BPB, TH, SMEM_BYTES>>>(mesh, finit);  // 16 clusters x 8 CTAs
    gather_kernel<<<BATCH, 1024>>>(mesh, out);
}

// round 7
// speedup vs baseline: 1.0472x; 1.0472x over previous
#include <cuda_runtime.h>
#include <stdint.h>

#define BATCH 16
#define NPTS  131072
#define NSAMP 1024
#define BPB   8                      // blocks per batch
#define PTS   (NPTS / BPB)           // 16384 points per block
#define TH    512                    // threads per block
#define NW    (TH / 32)              // 16 warps
#define KK    (PTS / (4 * TH))       // 8 x 4-point chunks per thread
#define SMEM_BYTES (PTS * 3 * (int)sizeof(float))   // 196608

#define OFF_SCALE (BATCH * NSAMP * 3)   // 49152
#define OFF_IDX   (OFF_SCALE + BATCH)   // 49168

typedef unsigned long long u64;
typedef unsigned int       u32;

// device scratch (no allocations allowed)
__device__ float4 g_cand[2][BATCH][BPB][2];  // {key_lo, key_hi, x, y} {z,...}
__device__ u32    g_cnt[BATCH];
__device__ int    g_idx[BATCH * NSAMP];
__device__ float  g_scale[BATCH];
__device__ float  g_psum[BATCH][BPB][3];
__device__ float  g_pmax[BATCH][BPB];

// ---------------------------------------------------------------------------
// helpers
// ---------------------------------------------------------------------------
__device__ __forceinline__ u64 add2(u64 a, u64 b) {
    u64 d; asm("add.rn.f32x2 %0,%1,%2;" : "=l"(d) : "l"(a), "l"(b)); return d;
}
__device__ __forceinline__ u64 mul2(u64 a, u64 b) {
    u64 d; asm("mul.rn.f32x2 %0,%1,%2;" : "=l"(d) : "l"(a), "l"(b)); return d;
}
__device__ __forceinline__ void unpack2(u64 v, int& lo, int& hi) {
    asm("mov.b64 {%0,%1},%2;" : "=r"(lo), "=r"(hi) : "l"(v));
}
__device__ __forceinline__ u64 bcast2(float v) {
    u32 b = __float_as_uint(v); return ((u64)b << 32) | (u64)b;
}
__device__ __forceinline__ u32 ld_acq(const u32* p) {
    u32 v; asm volatile("ld.acquire.gpu.global.u32 %0,[%1];" : "=r"(v) : "l"(p) : "memory");
    return v;
}
__device__ __forceinline__ void red_rel_add(u32* p, u32 v) {
    asm volatile("red.release.gpu.global.add.u32 [%0],%1;" :: "l"(p), "r"(v) : "memory");
}

// ---------------------------------------------------------------------------
// Scale pass 1: per-slice partial sums (deterministic tree)
// ---------------------------------------------------------------------------
__global__ void __launch_bounds__(512, 1)
scale1_kernel(const float* __restrict__ mesh)
{
    const int b = blockIdx.x / BPB, s = blockIdx.x % BPB, tid = threadIdx.x;
    const float* base = mesh + (size_t)b * NPTS * 3 + (size_t)s * PTS * 3;

    float sx = 0.f, sy = 0.f, sz = 0.f;
    for (int p = tid; p < PTS; p += 512) {
        const float* q = base + (size_t)p * 3;
        sx += q[0]; sy += q[1]; sz += q[2];
    }
    __shared__ float red[3][16];
    #pragma unroll
    for (int off = 16; off; off >>= 1) {
        sx += __shfl_xor_sync(0xffffffffu, sx, off);
        sy += __shfl_xor_sync(0xffffffffu, sy, off);
        sz += __shfl_xor_sync(0xffffffffu, sz, off);
    }
    const int w = tid >> 5, l = tid & 31;
    if (l == 0) { red[0][w] = sx; red[1][w] = sy; red[2][w] = sz; }
    __syncthreads();
    if (w == 0 && l < 16) {
        sx = red[0][l]; sy = red[1][l]; sz = red[2][l];
        #pragma unroll
        for (int off = 8; off; off >>= 1) {
            sx += __shfl_xor_sync(0xffffffffu, sx, off);
            sy += __shfl_xor_sync(0xffffffffu, sy, off);
            sz += __shfl_xor_sync(0xffffffffu, sz, off);
        }
        if (l == 0) {
            g_psum[b][s][0] = sx; g_psum[b][s][1] = sy; g_psum[b][s][2] = sz;
        }
    }
}

// ---------------------------------------------------------------------------
// Scale pass 2: finalize mean (fixed order), partial max of dist^2 per slice
// ---------------------------------------------------------------------------
__global__ void __launch_bounds__(512, 1)
scale2_kernel(const float* __restrict__ mesh)
{
    const int b = blockIdx.x / BPB, s = blockIdx.x % BPB, tid = threadIdx.x;

    float mx = 0.f, my = 0.f, mz = 0.f;
    #pragma unroll
    for (int i = 0; i < BPB; i++) {
        mx += g_psum[b][i][0]; my += g_psum[b][i][1]; mz += g_psum[b][i][2];
    }
    const float cx = mx * (1.0f / NPTS), cy = my * (1.0f / NPTS), cz = mz * (1.0f / NPTS);

    const float* base = mesh + (size_t)b * NPTS * 3 + (size_t)s * PTS * 3;
    float m = 0.f;
    for (int p = tid; p < PTS; p += 512) {
        const float* q = base + (size_t)p * 3;
        float dx = q[0] - cx, dy = q[1] - cy, dz = q[2] - cz;
        m = fmaxf(m, dx * dx + dy * dy + dz * dz);
    }
    __shared__ float red[16];
    #pragma unroll
    for (int off = 16; off; off >>= 1)
        m = fmaxf(m, __shfl_xor_sync(0xffffffffu, m, off));
    const int w = tid >> 5, l = tid & 31;
    if (l == 0) red[w] = m;
    __syncthreads();
    if (w == 0 && l < 16) {
        m = red[l];
        #pragma unroll
        for (int off = 8; off; off >>= 1)
            m = fmaxf(m, __shfl_xor_sync(0xffffffffu, m, off));
        if (l == 0) g_pmax[b][s] = m;
    }
}

// ---------------------------------------------------------------------------
// Scale pass 3: final max -> sqrt, write scale, reset FPS barrier counters
// ---------------------------------------------------------------------------
__global__ void scale3_kernel(float* __restrict__ out)
{
    const int b = blockIdx.x, l = threadIdx.x;
    float m = (l < BPB) ? g_pmax[b][l] : 0.f;
    #pragma unroll
    for (int off = 4; off; off >>= 1)
        m = fmaxf(m, __shfl_xor_sync(0xffffffffu, m, off));
    if (l == 0) {
        float sc = __fsqrt_rn(m);        // sqrt(max) == max(sqrt): monotone
        g_scale[b] = sc;
        out[OFF_SCALE + b] = sc;
        g_cnt[b] = 0;                    // reset FPS exchange counter
    }
}

// ---------------------------------------------------------------------------
// FPS: 8 cooperating blocks per batch, L2 exchange, de-serialized tail:
//  - one __syncthreads per iteration (skey visibility), nothing after exchange
//  - ALL warps redundantly level-2 reduce, poll the counter, and merge the 8
//    candidates from L2, so each warp resumes compute the moment data lands.
// ---------------------------------------------------------------------------
__global__ void __launch_bounds__(TH, 1)
fps_kernel(const float* __restrict__ mesh, const int* __restrict__ finit)
{
    extern __shared__ float sm[];
    float* sx = sm;
    float* sy = sm + PTS;
    float* sz = sm + 2 * PTS;

    const int blk = blockIdx.x;
    const int b = blk / BPB;
    const int s = blk - b * BPB;
    const int tid = threadIdx.x;
    const int w = tid >> 5, l = tid & 31;

    const float* mb = mesh + (size_t)b * NPTS * 3;

    // stage this block's xyz slice into SMEM (SoA, one-time)
    {
        const float* gsrc = mb + (size_t)s * PTS * 3;
        for (int e = tid; e < PTS * 3; e += TH) {
            float v = gsrc[e];
            int p = e / 3;
            int c = e - 3 * p;
            sm[c * PTS + p] = v;
        }
    }

    // per-thread min-distances as int bit patterns (all values >= 0)
    int di[4 * KK];
    #pragma unroll
    for (int k = 0; k < 4 * KK; k++) di[k] = __float_as_int(1e10f);

    int fidx = finit[b];
    float cx = mb[(size_t)fidx * 3 + 0];
    float cy = mb[(size_t)fidx * 3 + 1];
    float cz = mb[(size_t)fidx * 3 + 2];

    __shared__ u64 skey[NW];

    __syncthreads();

    const ulonglong2* sxp = (const ulonglong2*)sx;
    const ulonglong2* syp = (const ulonglong2*)sy;
    const ulonglong2* szp = (const ulonglong2*)sz;

    for (int t = 0; t < NSAMP; ++t) {
        if (s == 0 && tid == 0) g_idx[b * NSAMP + t] = fidx;   // record BEFORE update
        if (t == NSAMP - 1) break;

        const u64 ncx = bcast2(-cx), ncy = bcast2(-cy), ncz = bcast2(-cz);

        int bvi = -1;            // int compare == float compare for nonneg floats
        int bp  = 0x7fffffff;

        #pragma unroll
        for (int k = 0; k < KK; k++) {
            const int c = k * TH + tid;
            ulonglong2 X = sxp[c];
            ulonglong2 Y = syp[c];
            ulonglong2 Z = szp[c];
            const int base = s * PTS + 4 * c;
            {   // points base, base+1
                u64 dx = add2(X.x, ncx), dy = add2(Y.x, ncy), dz = add2(Z.x, ncz);
                u64 d2 = add2(add2(mul2(dx, dx), mul2(dy, dy)), mul2(dz, dz));
                int a0, a1; unpack2(d2, a0, a1);
                int n0 = min(a0, di[4 * k + 0]); di[4 * k + 0] = n0;
                int n1 = min(a1, di[4 * k + 1]); di[4 * k + 1] = n1;
                if (n0 > bvi) { bvi = n0; bp = base; }
                if (n1 > bvi) { bvi = n1; bp = base + 1; }
            }
            {   // points base+2, base+3
                u64 dx = add2(X.y, ncx), dy = add2(Y.y, ncy), dz = add2(Z.y, ncz);
                u64 d2 = add2(add2(mul2(dx, dx), mul2(dy, dy)), mul2(dz, dz));
                int a0, a1; unpack2(d2, a0, a1);
                int n0 = min(a0, di[4 * k + 2]); di[4 * k + 2] = n0;
                int n1 = min(a1, di[4 * k + 3]); di[4 * k + 3] = n1;
                if (n0 > bvi) { bvi = n0; bp = base + 2; }
                if (n1 > bvi) { bvi = n1; bp = base + 3; }
            }
        }

        // packed key: dist desc, index asc on ties -> single u64 max
        u64 key = ((u64)(u32)bvi << 32) | (u32)(~bp);
        #pragma unroll
        for (int off = 16; off; off >>= 1) {
            u64 ok = __shfl_down_sync(0xffffffffu, key, off);
            if (ok > key) key = ok;
        }
        if (l == 0) skey[w] = key;
        __syncthreads();                 // the ONLY block barrier in the iteration

        // level-2 reduce: every warp redundantly (identical result, parallel)
        key = skey[l & (NW - 1)];
        #pragma unroll
        for (int off = NW / 2; off; off >>= 1) {
            u64 ok = __shfl_down_sync(0xffffffffu, key, off, NW);
            if (ok > key) key = ok;
        }
        key = __shfl_sync(0xffffffffu, key, 0);       // block winner in all lanes

        const int par = t & 1;
        // warp NW-1 (arbiter-prioritized) publishes this CTA's candidate
        if (w == NW - 1 && l == 0) {
            const int gp = (int)(~(u32)key);          // global-in-batch index
            const int lp = gp - s * PTS;              // local -> SMEM coords
            __stcg(&g_cand[par][b][s][0],
                   make_float4(__uint_as_float((u32)key),
                               __uint_as_float((u32)(key >> 32)),
                               sx[lp], sy[lp]));
            __stcg(&g_cand[par][b][s][1], make_float4(sz[lp], 0.f, 0.f, 0.f));
            red_rel_add(&g_cnt[b], 1u);               // release-arrive
        }

        // every warp independently waits (all-lane coalesced acquire poll)
        const u32 target = (u32)(BPB * (t + 1));
        while (ld_acq(&g_cnt[b]) < target) { }

        // every warp redundantly merges the 8 candidates from L2
        float4 A  = __ldcg(&g_cand[par][b][l & 7][0]);
        float  Az = __ldcg(&g_cand[par][b][l & 7][1]).x;
        u64 mk = ((u64)__float_as_uint(A.y) << 32) | __float_as_uint(A.x);
        u64 m = mk;
        #pragma unroll
        for (int off = 4; off; off >>= 1) {
            u64 o = __shfl_down_sync(0xffffffffu, m, off, 8);
            if (o > m) m = o;
        }
        m = __shfl_sync(0xffffffffu, m, 0);          // winner key -> all lanes
        unsigned bal = __ballot_sync(0xffffffffu, mk == m) & 0xffu;
        int src = __ffs(bal) - 1;                    // keys unique (contain idx)
        cx = __shfl_sync(0xffffffffu, A.z, src);
        cy = __shfl_sync(0xffffffffu, A.w, src);
        cz = __shfl_sync(0xffffffffu, Az,  src);
        fidx = (int)(~(u32)m);
        // NO trailing __syncthreads: each warp proceeds immediately
    }
}

// ---------------------------------------------------------------------------
// Gather: sample points, normalize, emit idx as float
// ---------------------------------------------------------------------------
__global__ void __launch_bounds__(1024, 1)
gather_kernel(const float* __restrict__ mesh, float* __restrict__ out)
{
    const int b = blockIdx.x;
    const int j = threadIdx.x;
    const int i = g_idx[b * NSAMP + j];
    const float sc = g_scale[b];
    const float* q = mesh + ((size_t)b * NPTS + (size_t)i) * 3;
    const size_t o = ((size_t)b * NSAMP + j) * 3;
    out[o + 0] = __fdiv_rn(q[0], sc);
    out[o + 1] = __fdiv_rn(q[1], sc);
    out[o + 2] = __fdiv_rn(q[2], sc);
    out[OFF_IDX + b * NSAMP + j] = (float)i;   // exact: i < 2^24
}

// ---------------------------------------------------------------------------
extern "C" void kernel_launch(void* const* d_in, const int* in_sizes, int n_in,
                              void* d_out, int out_size)
{
    const float* mesh  = (const float*)d_in[0];
    const int*   finit = (const int*)d_in[1];
    float* out = (float*)d_out;

    cudaFuncSetAttribute(fps_kernel,
                         cudaFuncAttributeMaxDynamicSharedMemorySize, SMEM_BYTES);

    scale1_kernel<<<BATCH * BPB, 512>>>(mesh);
    scale2_kernel<<<BATCH * BPB, 512>>>(mesh);
    scale3_kernel<<<BATCH, 32>>>(out);                         // also resets g_cnt
    fps_kernel<<<BATCH * BPB, TH, SMEM_BYTES>>>(mesh, finit);  // 128 blocks co-resident
    gather_kernel<<<BATCH, 1024>>>(mesh, out);
}